// round 3
// baseline (speedup 1.0000x reference)
#include <cuda_runtime.h>
#include <cuda_fp16.h>
#include <cstdint>

// ---------------- problem dims ----------------
#define NB    8
#define HH    128
#define WW    128
#define CIN   64
#define COUT  128
#define ROWS_PER_VAR (NB*HH*WW)      // 131072
#define ALPHA 0.2f
#define EPS_BN 1e-3f

// ---------------- device globals (no allocs allowed) ----------------
// per-h basis matrices: [h][5 blocks][o=128][c=64] fp16  (10.5 MB)
__device__ __align__(16) __half g_Bh[(size_t)HH * 5 * COUT * CIN];
__device__ float g_sum[2 * COUT];
__device__ float g_sumsq[2 * COUT];

// ---------------- helpers ----------------
__device__ __forceinline__ uint32_t smem_u32(const void* p) {
    uint32_t a;
    asm("{ .reg .u64 t; cvta.to.shared.u64 t, %1; cvt.u32.u64 %0, t; }" : "=r"(a) : "l"(p));
    return a;
}

__device__ __forceinline__ void ldsm4(uint32_t& r0, uint32_t& r1, uint32_t& r2, uint32_t& r3,
                                      uint32_t addr) {
    asm volatile("ldmatrix.sync.aligned.m8n8.x4.shared.b16 {%0,%1,%2,%3}, [%4];"
                 : "=r"(r0), "=r"(r1), "=r"(r2), "=r"(r3) : "r"(addr));
}

__device__ __forceinline__ void mma16816(float* d, const uint32_t* a, const uint32_t* b) {
    asm volatile("mma.sync.aligned.m16n8k16.row.col.f32.f16.f16.f32 "
                 "{%0,%1,%2,%3}, {%4,%5,%6,%7}, {%8,%9}, {%0,%1,%2,%3};"
                 : "+f"(d[0]), "+f"(d[1]), "+f"(d[2]), "+f"(d[3])
                 : "r"(a[0]), "r"(a[1]), "r"(a[2]), "r"(a[3]), "r"(b[0]), "r"(b[1]));
}

__device__ __forceinline__ uint32_t packh2(float lo, float hi) {
    __half2 t = __floats2half2_rn(lo, hi);
    return *(uint32_t*)&t;
}

// ================= prep: per-h basis matrices (fp16), zero stats =================
// P_v(h)[c,o] = f[0,v,c,o] + ch1*f[1,v,c,o] + ch2*f[2,v,c,o]
// Q_v(h)[c,o] =              sh1*f[1,v,c,o] + sh2*f[2,v,c,o]
// block order: 0->P0, 1->P1, 2->Q1, 3->P2, 4->Q2; stored as [o][c] (n-major for mma B)
__global__ void __launch_bounds__(256) prep_B(const float* __restrict__ filters) {
    __shared__ float acc[CIN * 130];
    const int h = blockIdx.x;
    const int tid = threadIdx.x;
    if (h == 0 && tid < 2 * COUT) { g_sum[tid] = 0.0f; g_sumsq[tid] = 0.0f; }

    float c1, s1, c2, s2;
    sincospif((float)h * (1.0f / 64.0f), &s1, &c1);
    sincospif((float)h * (1.0f / 32.0f), &s2, &c2);
    const float cu[5][3] = {
        {1.f, c1, c2}, {1.f, c1, c2}, {0.f, s1, s2}, {1.f, c1, c2}, {0.f, s1, s2}};
    const int vsel[5] = {0, 1, 1, 2, 2};
    const int ustart[5] = {0, 0, 1, 0, 1};

    for (int vb = 0; vb < 5; ++vb) {
        const int v = vsel[vb];
#pragma unroll 8
        for (int j = 0; j < 8; ++j) {
            int i4 = tid + j * 256;               // 2048 float4 = one [c][o] plane
            int c = (4 * i4) >> 7;
            int o = (4 * i4) & 127;
            float4 a = make_float4(0.f, 0.f, 0.f, 0.f);
            for (int u = ustart[vb]; u < 3; ++u) {
                const float4* pl = (const float4*)(filters + (size_t)((u * 3 + v) * CIN) * COUT);
                float4 f = pl[i4];
                float w = cu[vb][u];
                a.x += w * f.x; a.y += w * f.y; a.z += w * f.z; a.w += w * f.w;
            }
            float* ap = &acc[c * 130 + o];
            ap[0] = a.x; ap[1] = a.y; ap[2] = a.z; ap[3] = a.w;
        }
        __syncthreads();
        __half* dst = g_Bh + ((size_t)(h * 5 + vb)) * (COUT * CIN);
#pragma unroll 4
        for (int j = 0; j < 4; ++j) {
            int q = tid + j * 256;                // 1024 uint4 = [o=128][c=64] halves
            int o = q >> 3;
            int cb = (q & 7) * 8;
            uint4 val;
            val.x = packh2(acc[(cb + 0) * 130 + o], acc[(cb + 1) * 130 + o]);
            val.y = packh2(acc[(cb + 2) * 130 + o], acc[(cb + 3) * 130 + o]);
            val.z = packh2(acc[(cb + 4) * 130 + o], acc[(cb + 5) * 130 + o]);
            val.w = packh2(acc[(cb + 6) * 130 + o], acc[(cb + 7) * 130 + o]);
            *(uint4*)(dst + (size_t)o * CIN + cb) = val;
        }
        __syncthreads();
    }
}

// ---------------- main smem layout (dynamic) ----------------
#define SM_COEF  0          // 5*128 floats = 2560
#define SM_STAT  2560       // 2 var * 2 stat * 128 floats = 2048
#define SM_XRI   8192       // [128 w][64 c] float2 {xs, xd} = 65536
#define SM_A     73728      // 128 rows x 128 B (fp16, swizzled) = 16384
#define SM_B     90112      // 128 rows x 128 B (fp16, swizzled) = 16384
#define SM_TOTAL 106496

// ================= main: GEMM (M=128,N=128,K=320) per (n,h), both variants =================
__global__ void __launch_bounds__(256, 2) fourier_main(const float* __restrict__ xr,
                                                       const float* __restrict__ xi,
                                                       float* __restrict__ out) {
    extern __shared__ char smem[];
    float* coefT = (float*)(smem + SM_COEF);
    float* sStat = (float*)(smem + SM_STAT);
    const uint32_t sb = smem_u32(smem);
    const uint32_t sbA = sb + SM_A;
    const uint32_t sbB = sb + SM_B;

    const int tid = threadIdx.x;
    const int wid = tid >> 5;
    const int l = tid & 31;
    const int wm = (wid & 3) * 32;          // warp M offset (w rows)
    const int wn = (wid >> 2) * 64;         // warp N offset (o cols)
    const int b = blockIdx.x;               // n*128 + h
    const int h = b & 127;

    // per-w coefficients for the 5 K-blocks
    if (tid < 128) {
        float cw1, sw1, cw2, sw2;
        sincospif((float)tid * (1.0f / 64.0f), &sw1, &cw1);
        sincospif((float)tid * (1.0f / 32.0f), &sw2, &cw2);
        coefT[0 * 128 + tid] = 1.0f;
        coefT[1 * 128 + tid] = cw1;
        coefT[2 * 128 + tid] = -sw1;
        coefT[3 * 128 + tid] = cw2;
        coefT[4 * 128 + tid] = -sw2;
    }
    // zero ALL 512 stat slots (256 threads -> 2 each). Stale smem on graph
    // replay was the R2 post-timing NaN.
    sStat[tid] = 0.0f;
    sStat[tid + 256] = 0.0f;

    // load input row-tile: xs = xr+xi, xd = xi-xr, as float2 pairs [w][c]
    {
        const float4* xr4 = (const float4*)(xr + (size_t)b * (WW * CIN));
        const float4* xi4 = (const float4*)(xi + (size_t)b * (WW * CIN));
        float4* XRI4 = (float4*)(smem + SM_XRI);
#pragma unroll 8
        for (int k = 0; k < 8; ++k) {
            int i4 = tid + k * 256;             // < 2048
            float4 r = xr4[i4];
            float4 m = xi4[i4];
            XRI4[2 * i4]     = make_float4(r.x + m.x, m.x - r.x, r.y + m.y, m.y - r.y);
            XRI4[2 * i4 + 1] = make_float4(r.z + m.z, m.z - r.z, r.w + m.w, m.w - r.w);
        }
    }

    const __half* Bh = g_Bh + (size_t)(h * 5) * (COUT * CIN);
    const float4* XRI4 = (const float4*)(smem + SM_XRI);

    for (int v = 0; v < 2; ++v) {
        float facc[2][8][4];
#pragma unroll
        for (int mt = 0; mt < 2; ++mt)
#pragma unroll
            for (int nt = 0; nt < 8; ++nt)
#pragma unroll
                for (int e = 0; e < 4; ++e) facc[mt][nt][e] = 0.0f;

        for (int kb = 0; kb < 5; ++kb) {
            __syncthreads();    // previous chunk fully consumed / XRI+coef ready
            // ---- build A chunk: A[w][k=64] = coef[kb][w] * x_v[w][c], fp16 swizzled ----
#pragma unroll 16
            for (int j = 0; j < 16; ++j) {
                int i = tid + j * 256;           // 4096 half2
                int row = i >> 5;
                int c2 = i & 31;
                float cf = coefT[kb * 128 + row];
                float4 x = XRI4[row * 32 + c2];  // {xs0, xd0, xs1, xd1}
                float p0 = v ? x.y : x.x;
                float p1 = v ? x.w : x.z;
                uint32_t hv = packh2(cf * p0, cf * p1);
                uint32_t bo = c2 * 4;
                uint32_t dst = row * 128 + ((((bo >> 4)) ^ (row & 7)) << 4) + (bo & 15);
                *(uint32_t*)(smem + SM_A + dst) = hv;
            }
            // ---- copy B chunk: g_Bh[h][kb][o][c] -> smem [o row][128B] swizzled ----
            {
                const __half* Bsrc = Bh + (size_t)kb * (COUT * CIN);
#pragma unroll 4
                for (int j = 0; j < 4; ++j) {
                    int i = tid + j * 256;       // 1024 uint4
                    int o = i >> 3;
                    int ch = i & 7;
                    uint4 val = *(const uint4*)(Bsrc + (size_t)o * CIN + ch * 8);
                    uint32_t dst = o * 128 + ((ch ^ (o & 7)) << 4);
                    *(uint4*)(smem + SM_B + dst) = val;
                }
            }
            __syncthreads();

            // ---- 4 k-steps of m16n8k16 over warp tile m32 x n64 ----
#pragma unroll 4
            for (int ks = 0; ks < 4; ++ks) {
                uint32_t bfr[8][2];
#pragma unroll 4
                for (int p = 0; p < 4; ++p) {    // n-tile pairs (16 n each)
                    int nrow = wn + p * 16 + (l & 15);
                    uint32_t addr = sbB + nrow * 128 +
                                    (((ks * 2 + (l >> 4)) ^ (nrow & 7)) << 4);
                    uint32_t r0, r1, r2, r3;
                    ldsm4(r0, r1, r2, r3, addr);
                    bfr[2 * p][0] = r0; bfr[2 * p][1] = r2;
                    bfr[2 * p + 1][0] = r1; bfr[2 * p + 1][1] = r3;
                }
                uint32_t afr[2][4];
#pragma unroll 2
                for (int mt = 0; mt < 2; ++mt) {
                    int arow = wm + mt * 16 + (l & 15);
                    uint32_t addr = sbA + arow * 128 +
                                    (((ks * 2 + (l >> 4)) ^ (arow & 7)) << 4);
                    ldsm4(afr[mt][0], afr[mt][1], afr[mt][2], afr[mt][3], addr);
                }
#pragma unroll 2
                for (int mt = 0; mt < 2; ++mt)
#pragma unroll 8
                    for (int nt = 0; nt < 8; ++nt)
                        mma16816(facc[mt][nt], afr[mt], bfr[nt]);
            }
        }

        // ---- epilogue: store raw out + fused per-channel stats ----
        float* obase = out + ((size_t)v * ROWS_PER_VAR + (size_t)b * 128) * COUT;
#pragma unroll 8
        for (int nt = 0; nt < 8; ++nt) {
            int c = wn + nt * 8 + 2 * (l & 3);
#pragma unroll 2
            for (int mt = 0; mt < 2; ++mt) {
                int r0 = wm + mt * 16 + (l >> 2);
                *(float2*)(obase + (size_t)r0 * COUT + c) =
                    make_float2(facc[mt][nt][0], facc[mt][nt][1]);
                *(float2*)(obase + (size_t)(r0 + 8) * COUT + c) =
                    make_float2(facc[mt][nt][2], facc[mt][nt][3]);
            }
            // stats: sum over this warp's 4 rows per col, reduce across row-lanes
            float a0 = facc[0][nt][0], a2 = facc[0][nt][2];
            float b0 = facc[1][nt][0], b2 = facc[1][nt][2];
            float a1 = facc[0][nt][1], a3 = facc[0][nt][3];
            float b1 = facc[1][nt][1], b3 = facc[1][nt][3];
            float s0 = a0 + a2 + b0 + b2;
            float q0 = a0 * a0 + a2 * a2 + b0 * b0 + b2 * b2;
            float s1 = a1 + a3 + b1 + b3;
            float q1 = a1 * a1 + a3 * a3 + b1 * b1 + b3 * b3;
#pragma unroll
            for (int off = 4; off < 32; off <<= 1) {
                s0 += __shfl_xor_sync(0xFFFFFFFFu, s0, off);
                q0 += __shfl_xor_sync(0xFFFFFFFFu, q0, off);
                s1 += __shfl_xor_sync(0xFFFFFFFFu, s1, off);
                q1 += __shfl_xor_sync(0xFFFFFFFFu, q1, off);
            }
            if (l < 4) {
                atomicAdd(&sStat[v * 256 + c], s0);
                atomicAdd(&sStat[v * 256 + c + 1], s1);
                atomicAdd(&sStat[v * 256 + 128 + c], q0);
                atomicAdd(&sStat[v * 256 + 128 + c + 1], q1);
            }
        }
    }

    __syncthreads();
    if (tid < 256) {
        atomicAdd(&g_sum[tid], sStat[(tid >> 7) * 256 + (tid & 127)]);
        atomicAdd(&g_sumsq[tid], sStat[(tid >> 7) * 256 + 128 + (tid & 127)]);
    }
}

// ================= normalize: BN(train) + LeakyReLU, in place =================
__global__ void __launch_bounds__(256) norm_kernel(float* __restrict__ out,
                                                   const float* __restrict__ gr,
                                                   const float* __restrict__ br,
                                                   const float* __restrict__ gi,
                                                   const float* __restrict__ bi) {
    __shared__ float sA[2 * COUT], sB[2 * COUT];
    const int tid = threadIdx.x;
    {
        int v = tid >> 7, o = tid & 127;
        const float inv = 1.0f / (float)ROWS_PER_VAR;
        float mean = g_sum[tid] * inv;
        float var  = g_sumsq[tid] * inv - mean * mean;
        float g  = v ? gi[o] : gr[o];
        float be = v ? bi[o] : br[o];
        float a = g * rsqrtf(var + EPS_BN);
        sA[tid] = a;
        sB[tid] = be - mean * a;
    }
    __syncthreads();
    float4* p = (float4*)out;
    const int base = blockIdx.x * 256 + tid;
#pragma unroll 4
    for (int k = 0; k < 4; ++k) {
        int i4 = base + k * 2097152;          // gridDim(8192)*256
        float4 x = p[i4];
        int idx = ((i4 >= 4194304) ? COUT : 0) + ((i4 * 4) & 127);
        float r0 = fmaf(sA[idx + 0], x.x, sB[idx + 0]);
        float r1 = fmaf(sA[idx + 1], x.y, sB[idx + 1]);
        float r2 = fmaf(sA[idx + 2], x.z, sB[idx + 2]);
        float r3 = fmaf(sA[idx + 3], x.w, sB[idx + 3]);
        x.x = r0 >= 0.f ? r0 : ALPHA * r0;
        x.y = r1 >= 0.f ? r1 : ALPHA * r1;
        x.z = r2 >= 0.f ? r2 : ALPHA * r2;
        x.w = r3 >= 0.f ? r3 : ALPHA * r3;
        p[i4] = x;
    }
}

// ================= launch =================
extern "C" void kernel_launch(void* const* d_in, const int* in_sizes, int n_in,
                              void* d_out, int out_size) {
    const float* xr = (const float*)d_in[0];
    const float* xi = (const float*)d_in[1];
    const float* fl = (const float*)d_in[2];
    const float* gr = (const float*)d_in[3];
    const float* br = (const float*)d_in[4];
    const float* gi = (const float*)d_in[5];
    const float* bi = (const float*)d_in[6];
    float* out = (float*)d_out;

    cudaFuncSetAttribute(fourier_main, cudaFuncAttributeMaxDynamicSharedMemorySize, SM_TOTAL);

    prep_B<<<HH, 256>>>(fl);
    fourier_main<<<NB * HH, 256, SM_TOTAL>>>(xr, xi, out);
    norm_kernel<<<8192, 256>>>(out, gr, br, gi, bi);
}

// round 4
// speedup vs baseline: 1.1891x; 1.1891x over previous
#include <cuda_runtime.h>
#include <cuda_fp16.h>
#include <cstdint>

// ---------------- problem dims ----------------
#define NB    8
#define HH    128
#define WW    128
#define CIN   64
#define COUT  128
#define ROWS_PER_VAR (NB*HH*WW)      // 131072
#define ALPHA 0.2f
#define EPS_BN 1e-3f

// ---------------- device globals (no allocs allowed) ----------------
__device__ __align__(16) float  g_fT[9 * COUT * CIN];                 // [uv][o][c] fp32
__device__ __align__(16) __half g_Bh[(size_t)HH * 5 * COUT * CIN];    // [h][vb][o][c] fp16
__device__ __align__(16) __half g_raw[(size_t)2 * ROWS_PER_VAR * COUT]; // fp16 raw GEMM out
__device__ float g_sum[2 * COUT];
__device__ float g_sumsq[2 * COUT];

// ---------------- helpers ----------------
__device__ __forceinline__ uint32_t smem_u32(const void* p) {
    uint32_t a;
    asm("{ .reg .u64 t; cvta.to.shared.u64 t, %1; cvt.u32.u64 %0, t; }" : "=r"(a) : "l"(p));
    return a;
}

__device__ __forceinline__ void ldsm4(uint32_t& r0, uint32_t& r1, uint32_t& r2, uint32_t& r3,
                                      uint32_t addr) {
    asm volatile("ldmatrix.sync.aligned.m8n8.x4.shared.b16 {%0,%1,%2,%3}, [%4];"
                 : "=r"(r0), "=r"(r1), "=r"(r2), "=r"(r3) : "r"(addr));
}

__device__ __forceinline__ void mma16816(float* d, const uint32_t* a, const uint32_t* b) {
    asm volatile("mma.sync.aligned.m16n8k16.row.col.f32.f16.f16.f32 "
                 "{%0,%1,%2,%3}, {%4,%5,%6,%7}, {%8,%9}, {%0,%1,%2,%3};"
                 : "+f"(d[0]), "+f"(d[1]), "+f"(d[2]), "+f"(d[3])
                 : "r"(a[0]), "r"(a[1]), "r"(a[2]), "r"(a[3]), "r"(b[0]), "r"(b[1]));
}

__device__ __forceinline__ uint32_t packh2(float lo, float hi) {
    __half2 t = __floats2half2_rn(lo, hi);
    return *(uint32_t*)&t;
}

// ================= prep 1: transpose filters [uv][c][o] -> g_fT[uv][o][c]; zero stats =====
__global__ void __launch_bounds__(256) prep_T(const float* __restrict__ filters) {
    __shared__ float tile[COUT * 65];
    const int uv = blockIdx.x;          // 0..8
    const int tid = threadIdx.x;
    if (uv == 0) { g_sum[tid] = 0.0f; g_sumsq[tid] = 0.0f; }
    const float* src = filters + (size_t)uv * (CIN * COUT);
#pragma unroll 32
    for (int j = 0; j < 32; ++j) {
        int idx = tid + j * 256;        // < 8192, c = idx>>7, o = idx&127
        tile[(idx & 127) * 65 + (idx >> 7)] = src[idx];
    }
    __syncthreads();
    float* dst = g_fT + (size_t)uv * (COUT * CIN);
#pragma unroll 32
    for (int j = 0; j < 32; ++j) {
        int idx = tid + j * 256;        // o = idx>>6, c = idx&63
        dst[idx] = tile[(idx >> 6) * 65 + (idx & 63)];
    }
}

// ================= prep 2: stream per-(h, basis) matrices to fp16 ==================
// vb: 0->P0(v=0), 1->P1(v=1), 2->Q1(v=1), 3->P2(v=2), 4->Q2(v=2)
__global__ void __launch_bounds__(256) prep_B2() {
    const int hb = blockIdx.x;          // h*5 + vb
    const int h = hb / 5;
    const int vb = hb - 5 * h;
    const int tid = threadIdx.x;
    const int v = (vb == 0) ? 0 : ((vb <= 2) ? 1 : 2);
    const bool sinb = (vb == 2) || (vb == 4);

    float c1, s1, c2, s2;
    sincospif((float)h * (1.0f / 64.0f), &s1, &c1);
    sincospif((float)h * (1.0f / 32.0f), &s2, &c2);
    const float w0 = sinb ? 0.0f : 1.0f;
    const float w1 = sinb ? s1 : c1;
    const float w2 = sinb ? s2 : c2;

    const float4* p0 = (const float4*)(g_fT + (size_t)(0 * 3 + v) * (COUT * CIN));
    const float4* p1 = (const float4*)(g_fT + (size_t)(1 * 3 + v) * (COUT * CIN));
    const float4* p2 = (const float4*)(g_fT + (size_t)(2 * 3 + v) * (COUT * CIN));
    __half* dst = g_Bh + (size_t)hb * (COUT * CIN);

#pragma unroll 4
    for (int j = 0; j < 4; ++j) {
        int g = tid + j * 256;          // < 1024 uint4 groups (8 halves)
        int f4 = g * 2;                 // float4 index
#pragma unroll 2
        for (int q = 0; q < 2; ++q) {
            float4 a = p0[f4 + q];
            float4 b = p1[f4 + q];
            float4 c = p2[f4 + q];
            float r0 = w0 * a.x + w1 * b.x + w2 * c.x;
            float r1 = w0 * a.y + w1 * b.y + w2 * c.y;
            float r2 = w0 * a.z + w1 * b.z + w2 * c.z;
            float r3 = w0 * a.w + w1 * b.w + w2 * c.w;
            *(uint2*)(dst + (size_t)g * 8 + q * 4) =
                make_uint2(packh2(r0, r1), packh2(r2, r3));
        }
    }
}

// ---------------- main smem layout (dynamic) ----------------
#define SM_COEF  0          // 5*128 floats = 2560
#define SM_STAT  2560       // 512 floats = 2048
#define SM_XRI   8192       // [128 w][64 c] {xs,xd} float pairs = 65536
#define SM_AS    73728      // 128 x 128B fp16 swizzled (sum variant)
#define SM_AD    90112      // 128 x 128B fp16 swizzled (dif variant)
#define SM_B     106496     // 128 x 128B fp16 swizzled
#define SM_TOTAL 122880

// epilogue helper: store fp16 raw + fused per-channel stats (inlined, facc stays in regs)
__device__ __forceinline__ void epi_store(const float facc[2][8][4], __half* rbase,
                                          float* sStatv, int wm, int wn, int l) {
#pragma unroll
    for (int nt = 0; nt < 8; ++nt) {
        int c = wn + nt * 8 + 2 * (l & 3);
#pragma unroll
        for (int mt = 0; mt < 2; ++mt) {
            int r0 = wm + mt * 16 + (l >> 2);
            *(uint32_t*)(rbase + (size_t)r0 * COUT + c) =
                packh2(facc[mt][nt][0], facc[mt][nt][1]);
            *(uint32_t*)(rbase + (size_t)(r0 + 8) * COUT + c) =
                packh2(facc[mt][nt][2], facc[mt][nt][3]);
        }
        float a0 = facc[0][nt][0], a2 = facc[0][nt][2];
        float b0 = facc[1][nt][0], b2 = facc[1][nt][2];
        float a1 = facc[0][nt][1], a3 = facc[0][nt][3];
        float b1 = facc[1][nt][1], b3 = facc[1][nt][3];
        float s0 = a0 + a2 + b0 + b2;
        float q0 = a0 * a0 + a2 * a2 + b0 * b0 + b2 * b2;
        float s1 = a1 + a3 + b1 + b3;
        float q1 = a1 * a1 + a3 * a3 + b1 * b1 + b3 * b3;
#pragma unroll
        for (int off = 4; off < 32; off <<= 1) {
            s0 += __shfl_xor_sync(0xFFFFFFFFu, s0, off);
            q0 += __shfl_xor_sync(0xFFFFFFFFu, q0, off);
            s1 += __shfl_xor_sync(0xFFFFFFFFu, s1, off);
            q1 += __shfl_xor_sync(0xFFFFFFFFu, q1, off);
        }
        if (l < 4) {
            atomicAdd(&sStatv[c], s0);
            atomicAdd(&sStatv[c + 1], s1);
            atomicAdd(&sStatv[128 + c], q0);
            atomicAdd(&sStatv[128 + c + 1], q1);
        }
    }
}

// ================= main: GEMM (M=128,N=128,K=320) per (n,h), both variants in one pass ====
__global__ void __launch_bounds__(256) fourier_main(const float* __restrict__ xr,
                                                    const float* __restrict__ xi) {
    extern __shared__ char smem[];
    float* coefT = (float*)(smem + SM_COEF);
    float* sStat = (float*)(smem + SM_STAT);
    const uint32_t sb = smem_u32(smem);
    const uint32_t sbAS = sb + SM_AS;
    const uint32_t sbAD = sb + SM_AD;
    const uint32_t sbB = sb + SM_B;

    const int tid = threadIdx.x;
    const int wid = tid >> 5;
    const int l = tid & 31;
    const int wm = (wid & 3) * 32;
    const int wn = (wid >> 2) * 64;
    const int b = blockIdx.x;           // n*128 + h
    const int h = b & 127;

    if (tid < 128) {
        float cw1, sw1, cw2, sw2;
        sincospif((float)tid * (1.0f / 64.0f), &sw1, &cw1);
        sincospif((float)tid * (1.0f / 32.0f), &sw2, &cw2);
        coefT[0 * 128 + tid] = 1.0f;
        coefT[1 * 128 + tid] = cw1;
        coefT[2 * 128 + tid] = -sw1;
        coefT[3 * 128 + tid] = cw2;
        coefT[4 * 128 + tid] = -sw2;
    }
    sStat[tid] = 0.0f;
    sStat[tid + 256] = 0.0f;

    // load input tile: xs = xr+xi, xd = xi-xr, interleaved per channel pair
    {
        const float4* xr4 = (const float4*)(xr + (size_t)b * (WW * CIN));
        const float4* xi4 = (const float4*)(xi + (size_t)b * (WW * CIN));
        float4* XRI4w = (float4*)(smem + SM_XRI);
#pragma unroll 8
        for (int k = 0; k < 8; ++k) {
            int i4 = tid + k * 256;
            float4 r = xr4[i4];
            float4 m = xi4[i4];
            XRI4w[2 * i4]     = make_float4(r.x + m.x, m.x - r.x, r.y + m.y, m.y - r.y);
            XRI4w[2 * i4 + 1] = make_float4(r.z + m.z, m.z - r.z, r.w + m.w, m.w - r.w);
        }
    }

    const __half* Bh = g_Bh + (size_t)(h * 5) * (COUT * CIN);
    const float4* XRI4 = (const float4*)(smem + SM_XRI);

    float faccS[2][8][4], faccD[2][8][4];
#pragma unroll
    for (int mt = 0; mt < 2; ++mt)
#pragma unroll
        for (int nt = 0; nt < 8; ++nt)
#pragma unroll
            for (int e = 0; e < 4; ++e) { faccS[mt][nt][e] = 0.0f; faccD[mt][nt][e] = 0.0f; }

    for (int kb = 0; kb < 5; ++kb) {
        __syncthreads();    // previous chunk consumed / XRI+coef visible
        // ---- build BOTH A chunks from one XRI read ----
#pragma unroll 16
        for (int j = 0; j < 16; ++j) {
            int i = tid + j * 256;           // 4096 half2 per buffer
            int row = i >> 5;
            int c2 = i & 31;
            float cf = coefT[kb * 128 + row];
            float4 x = XRI4[row * 32 + c2];  // {xs0, xd0, xs1, xd1}
            uint32_t hs = packh2(cf * x.x, cf * x.z);
            uint32_t hd = packh2(cf * x.y, cf * x.w);
            uint32_t bo = c2 * 4;
            uint32_t dst = row * 128 + (((bo >> 4) ^ (row & 7)) << 4) + (bo & 15);
            *(uint32_t*)(smem + SM_AS + dst) = hs;
            *(uint32_t*)(smem + SM_AD + dst) = hd;
        }
        // ---- B chunk once per kb ----
        {
            const __half* Bsrc = Bh + (size_t)kb * (COUT * CIN);
#pragma unroll 4
            for (int j = 0; j < 4; ++j) {
                int i = tid + j * 256;       // 1024 uint4
                int o = i >> 3;
                int ch = i & 7;
                uint4 val = *(const uint4*)(Bsrc + (size_t)o * CIN + ch * 8);
                uint32_t dst = o * 128 + ((ch ^ (o & 7)) << 4);
                *(uint4*)(smem + SM_B + dst) = val;
            }
        }
        __syncthreads();

        // ---- 4 k-steps; B fragments shared by both variants ----
#pragma unroll 4
        for (int ks = 0; ks < 4; ++ks) {
            uint32_t bfr[8][2];
#pragma unroll 4
            for (int p = 0; p < 4; ++p) {
                int nrow = wn + p * 16 + (l & 15);
                uint32_t addr = sbB + nrow * 128 +
                                (((ks * 2 + (l >> 4)) ^ (nrow & 7)) << 4);
                uint32_t r0, r1, r2, r3;
                ldsm4(r0, r1, r2, r3, addr);
                bfr[2 * p][0] = r0; bfr[2 * p][1] = r2;
                bfr[2 * p + 1][0] = r1; bfr[2 * p + 1][1] = r3;
            }
            uint32_t afrS[2][4], afrD[2][4];
#pragma unroll 2
            for (int mt = 0; mt < 2; ++mt) {
                int arow = wm + mt * 16 + (l & 15);
                uint32_t off = arow * 128 + (((ks * 2 + (l >> 4)) ^ (arow & 7)) << 4);
                ldsm4(afrS[mt][0], afrS[mt][1], afrS[mt][2], afrS[mt][3], sbAS + off);
                ldsm4(afrD[mt][0], afrD[mt][1], afrD[mt][2], afrD[mt][3], sbAD + off);
            }
#pragma unroll 2
            for (int mt = 0; mt < 2; ++mt)
#pragma unroll 8
                for (int nt = 0; nt < 8; ++nt) {
                    mma16816(faccS[mt][nt], afrS[mt], bfr[nt]);
                    mma16816(faccD[mt][nt], afrD[mt], bfr[nt]);
                }
        }
    }

    // ---- epilogue: fp16 raw + fused stats for both variants ----
    epi_store(faccS, g_raw + (size_t)b * 128 * COUT, sStat, wm, wn, l);
    epi_store(faccD, g_raw + ((size_t)ROWS_PER_VAR + (size_t)b * 128) * COUT,
              sStat + 256, wm, wn, l);

    __syncthreads();
    atomicAdd(&g_sum[tid], sStat[(tid >> 7) * 256 + (tid & 127)]);
    atomicAdd(&g_sumsq[tid], sStat[(tid >> 7) * 256 + 128 + (tid & 127)]);
}

// ================= normalize: BN(train) + LeakyReLU, fp16 raw -> fp32 out =================
__global__ void __launch_bounds__(256) norm_kernel(float* __restrict__ out,
                                                   const float* __restrict__ gr,
                                                   const float* __restrict__ br,
                                                   const float* __restrict__ gi,
                                                   const float* __restrict__ bi) {
    __shared__ float sA[2 * COUT], sB[2 * COUT];
    const int tid = threadIdx.x;
    {
        int v = tid >> 7, o = tid & 127;
        const float inv = 1.0f / (float)ROWS_PER_VAR;
        float mean = g_sum[tid] * inv;
        float var  = g_sumsq[tid] * inv - mean * mean;
        float g  = v ? gi[o] : gr[o];
        float be = v ? bi[o] : br[o];
        float a = g * rsqrtf(var + EPS_BN);
        sA[tid] = a;
        sB[tid] = be - mean * a;
    }
    __syncthreads();
    const uint4* rp = (const uint4*)g_raw;
    float4* op = (float4*)out;
    const int base = blockIdx.x * 256 + tid;      // grid 2048
#pragma unroll 8
    for (int k = 0; k < 8; ++k) {
        int i8 = base + k * 524288;               // < 4194304 (uint4 = 8 halves)
        uint4 rv = rp[i8];
        int idx = ((i8 >= 2097152) ? 128 : 0) + ((i8 & 15) * 8);
        float2 f0 = __half22float2(*(__half2*)&rv.x);
        float2 f1 = __half22float2(*(__half2*)&rv.y);
        float2 f2 = __half22float2(*(__half2*)&rv.z);
        float2 f3 = __half22float2(*(__half2*)&rv.w);
        float y0 = fmaf(sA[idx + 0], f0.x, sB[idx + 0]);
        float y1 = fmaf(sA[idx + 1], f0.y, sB[idx + 1]);
        float y2 = fmaf(sA[idx + 2], f1.x, sB[idx + 2]);
        float y3 = fmaf(sA[idx + 3], f1.y, sB[idx + 3]);
        float y4 = fmaf(sA[idx + 4], f2.x, sB[idx + 4]);
        float y5 = fmaf(sA[idx + 5], f2.y, sB[idx + 5]);
        float y6 = fmaf(sA[idx + 6], f3.x, sB[idx + 6]);
        float y7 = fmaf(sA[idx + 7], f3.y, sB[idx + 7]);
        y0 = y0 >= 0.f ? y0 : ALPHA * y0;
        y1 = y1 >= 0.f ? y1 : ALPHA * y1;
        y2 = y2 >= 0.f ? y2 : ALPHA * y2;
        y3 = y3 >= 0.f ? y3 : ALPHA * y3;
        y4 = y4 >= 0.f ? y4 : ALPHA * y4;
        y5 = y5 >= 0.f ? y5 : ALPHA * y5;
        y6 = y6 >= 0.f ? y6 : ALPHA * y6;
        y7 = y7 >= 0.f ? y7 : ALPHA * y7;
        op[2 * i8]     = make_float4(y0, y1, y2, y3);
        op[2 * i8 + 1] = make_float4(y4, y5, y6, y7);
    }
}

// ================= launch =================
extern "C" void kernel_launch(void* const* d_in, const int* in_sizes, int n_in,
                              void* d_out, int out_size) {
    const float* xr = (const float*)d_in[0];
    const float* xi = (const float*)d_in[1];
    const float* fl = (const float*)d_in[2];
    const float* gr = (const float*)d_in[3];
    const float* br = (const float*)d_in[4];
    const float* gi = (const float*)d_in[5];
    const float* bi = (const float*)d_in[6];
    float* out = (float*)d_out;

    cudaFuncSetAttribute(fourier_main, cudaFuncAttributeMaxDynamicSharedMemorySize, SM_TOTAL);

    prep_T<<<9, 256>>>(fl);
    prep_B2<<<5 * HH, 256>>>();
    fourier_main<<<NB * HH, 256, SM_TOTAL>>>(xr, xi);
    norm_kernel<<<2048, 256>>>(out, gr, br, gi, bi);
}

// round 6
// speedup vs baseline: 1.4065x; 1.1827x over previous
#include <cuda_runtime.h>
#include <cuda_fp16.h>
#include <cstdint>

// ---------------- problem dims ----------------
#define NB    8
#define HH    128
#define WW    128
#define CIN   64
#define COUT  128
#define ROWS_PER_VAR (NB*HH*WW)      // 131072
#define ALPHA 0.2f
#define EPS_BN 1e-3f

// ---------------- device globals (no allocs allowed) ----------------
__device__ __align__(16) float  g_fT[9 * COUT * CIN];                 // [uv][o][c] fp32
__device__ __align__(16) __half g_Bh[(size_t)HH * 5 * COUT * CIN];    // [h][vb][o][c] fp16
__device__ __align__(16) __half g_raw[(size_t)2 * ROWS_PER_VAR * COUT]; // fp16 raw GEMM out
__device__ float g_sum[2 * COUT];
__device__ float g_sumsq[2 * COUT];

// ---------------- helpers ----------------
__device__ __forceinline__ uint32_t smem_u32(const void* p) {
    uint32_t a;
    asm("{ .reg .u64 t; cvta.to.shared.u64 t, %1; cvt.u32.u64 %0, t; }" : "=r"(a) : "l"(p));
    return a;
}

__device__ __forceinline__ void ldsm4(uint32_t& r0, uint32_t& r1, uint32_t& r2, uint32_t& r3,
                                      uint32_t addr) {
    asm volatile("ldmatrix.sync.aligned.m8n8.x4.shared.b16 {%0,%1,%2,%3}, [%4];"
                 : "=r"(r0), "=r"(r1), "=r"(r2), "=r"(r3) : "r"(addr));
}

__device__ __forceinline__ void mma16816(float* d, const uint32_t* a, const uint32_t* b) {
    asm volatile("mma.sync.aligned.m16n8k16.row.col.f32.f16.f16.f32 "
                 "{%0,%1,%2,%3}, {%4,%5,%6,%7}, {%8,%9}, {%0,%1,%2,%3};"
                 : "+f"(d[0]), "+f"(d[1]), "+f"(d[2]), "+f"(d[3])
                 : "r"(a[0]), "r"(a[1]), "r"(a[2]), "r"(a[3]), "r"(b[0]), "r"(b[1]));
}

__device__ __forceinline__ uint32_t packh2(float lo, float hi) {
    __half2 t = __floats2half2_rn(lo, hi);
    return *(uint32_t*)&t;
}

__device__ __forceinline__ uint32_t bcasth2(float x) {
    __half h = __float2half_rn(x);
    __half2 t = __half2half2(h);
    return *(uint32_t*)&t;
}

__device__ __forceinline__ uint32_t hmul2u(uint32_t a, uint32_t b) {
    __half2 r = __hmul2(*(__half2*)&a, *(__half2*)&b);
    return *(uint32_t*)&r;
}

__device__ __forceinline__ void cp_async16(uint32_t dst_smem, const void* src) {
    asm volatile("cp.async.cg.shared.global [%0], [%1], 16;"
                 :: "r"(dst_smem), "l"(src) : "memory");
}
#define CP_ASYNC_COMMIT() asm volatile("cp.async.commit_group;" ::: "memory")
#define CP_ASYNC_WAIT1()  asm volatile("cp.async.wait_group 1;" ::: "memory")
#define CP_ASYNC_WAIT0()  asm volatile("cp.async.wait_group 0;" ::: "memory")

// ================= prep 1: transpose filters [uv][c][o] -> g_fT[uv][o][c]; zero stats =====
__global__ void __launch_bounds__(256) prep_T(const float* __restrict__ filters) {
    __shared__ float tile[COUT * 65];
    const int uv = blockIdx.x;          // 0..8
    const int tid = threadIdx.x;
    if (uv == 0) { g_sum[tid] = 0.0f; g_sumsq[tid] = 0.0f; }
    const float* src = filters + (size_t)uv * (CIN * COUT);
#pragma unroll 32
    for (int j = 0; j < 32; ++j) {
        int idx = tid + j * 256;
        tile[(idx & 127) * 65 + (idx >> 7)] = src[idx];
    }
    __syncthreads();
    float* dst = g_fT + (size_t)uv * (COUT * CIN);
#pragma unroll 32
    for (int j = 0; j < 32; ++j) {
        int idx = tid + j * 256;
        dst[idx] = tile[(idx >> 6) * 65 + (idx & 63)];
    }
}

// ================= prep 2: stream per-(h, basis) matrices to fp16 ==================
__global__ void __launch_bounds__(256) prep_B2() {
    const int hb = blockIdx.x;          // h*5 + vb
    const int h = hb / 5;
    const int vb = hb - 5 * h;
    const int tid = threadIdx.x;
    const int v = (vb == 0) ? 0 : ((vb <= 2) ? 1 : 2);
    const bool sinb = (vb == 2) || (vb == 4);

    float c1, s1, c2, s2;
    sincospif((float)h * (1.0f / 64.0f), &s1, &c1);
    sincospif((float)h * (1.0f / 32.0f), &s2, &c2);
    const float w0 = sinb ? 0.0f : 1.0f;
    const float w1 = sinb ? s1 : c1;
    const float w2 = sinb ? s2 : c2;

    const float4* p0 = (const float4*)(g_fT + (size_t)(0 * 3 + v) * (COUT * CIN));
    const float4* p1 = (const float4*)(g_fT + (size_t)(1 * 3 + v) * (COUT * CIN));
    const float4* p2 = (const float4*)(g_fT + (size_t)(2 * 3 + v) * (COUT * CIN));
    __half* dst = g_Bh + (size_t)hb * (COUT * CIN);

#pragma unroll 4
    for (int j = 0; j < 4; ++j) {
        int g = tid + j * 256;
        int f4 = g * 2;
#pragma unroll 2
        for (int q = 0; q < 2; ++q) {
            float4 a = p0[f4 + q];
            float4 b = p1[f4 + q];
            float4 c = p2[f4 + q];
            float r0 = w0 * a.x + w1 * b.x + w2 * c.x;
            float r1 = w0 * a.y + w1 * b.y + w2 * c.y;
            float r2 = w0 * a.z + w1 * b.z + w2 * c.z;
            float r3 = w0 * a.w + w1 * b.w + w2 * c.w;
            *(uint2*)(dst + (size_t)g * 8 + q * 4) =
                make_uint2(packh2(r0, r1), packh2(r2, r3));
        }
    }
}

// ---------------- main smem layout ----------------
#define SMX_XS   0          // 64 rows x 128B fp16 swizzled (sum variant)   = 8192
#define SMX_XD   8192       // 64 rows x 128B fp16 swizzled (dif variant)   = 8192
#define SMX_B    16384      // 2 stages x (128 rows x 128B)                 = 32768
#define SMX_STAT 49152      // 512 floats                                   = 2048
#define SMX_TOTAL 51200

// ================= main: per CTA = (n,h, M-half); A rescaled in registers per kb =========
__global__ void __launch_bounds__(256, 2) fourier_main(const float* __restrict__ xr,
                                                       const float* __restrict__ xi) {
    extern __shared__ char smem[];
    float* sStat = (float*)(smem + SMX_STAT);
    const uint32_t sb = smem_u32(smem);

    const int tid = threadIdx.x;
    const int wid = tid >> 5;
    const int l = tid & 31;
    const int v = wid >> 2;             // 0 = real(sum), 1 = imag(dif)
    const int wm = (wid & 3) * 16;      // warp M tile within the 64-row half
    const int bid = blockIdx.x;
    const int b = bid >> 1;             // n*128 + h
    const int mhalf = bid & 1;
    const int h = b & 127;

    sStat[tid] = 0.0f;
    sStat[tid + 256] = 0.0f;

    // ---- prefetch B stages 0 and 1 via cp.async ----
    const __half* BhBase = g_Bh + (size_t)(h * 5) * (COUT * CIN);
    {
#pragma unroll 2
        for (int s = 0; s < 2; ++s) {
            const __half* Bsrc = BhBase + (size_t)s * (COUT * CIN);
            uint32_t sdst = sb + SMX_B + s * 16384;
#pragma unroll 4
            for (int j = 0; j < 4; ++j) {
                int i = tid + j * 256;          // < 1024
                int o = i >> 3, ch = i & 7;
                cp_async16(sdst + o * 128 + ((ch ^ (o & 7)) << 4),
                           Bsrc + (size_t)o * CIN + ch * 8);
            }
            CP_ASYNC_COMMIT();
        }
    }

    // ---- build XS/XD (64 rows x 64 c, fp16 swizzled) from global x ----
    {
        const float4* xr4 = (const float4*)(xr + ((size_t)b * 128 + mhalf * 64) * CIN);
        const float4* xi4 = (const float4*)(xi + ((size_t)b * 128 + mhalf * 64) * CIN);
#pragma unroll 4
        for (int j = 0; j < 4; ++j) {
            int i4 = tid + j * 256;             // < 1024
            int row = i4 >> 4, cq = i4 & 15;
            float4 r = xr4[i4];
            float4 m = xi4[i4];
            uint2 hs = make_uint2(packh2(r.x + m.x, r.y + m.y), packh2(r.z + m.z, r.w + m.w));
            uint2 hd = make_uint2(packh2(m.x - r.x, m.y - r.y), packh2(m.z - r.z, m.w - r.w));
            uint32_t dst = row * 128 + (((cq >> 1) ^ (row & 7)) << 4) + (cq & 1) * 8;
            *(uint2*)(smem + SMX_XS + dst) = hs;
            *(uint2*)(smem + SMX_XD + dst) = hd;
        }
    }

    // ---- per-lane cf table (rows are fixed per lane across whole kernel) ----
    uint32_t cf[4][2];                  // [kb-1][reg parity]; kb0 has cf=1
    {
        int r0 = mhalf * 64 + wm + (l >> 2);
        float c1a, s1a, c1b, s1b, c2a, s2a, c2b, s2b;
        sincospif((float)r0 * (1.0f / 64.0f), &s1a, &c1a);
        sincospif((float)(r0 + 8) * (1.0f / 64.0f), &s1b, &c1b);
        sincospif((float)r0 * (1.0f / 32.0f), &s2a, &c2a);
        sincospif((float)(r0 + 8) * (1.0f / 32.0f), &s2b, &c2b);
        cf[0][0] = bcasth2(c1a);  cf[0][1] = bcasth2(c1b);
        cf[1][0] = bcasth2(-s1a); cf[1][1] = bcasth2(-s1b);
        cf[2][0] = bcasth2(c2a);  cf[2][1] = bcasth2(c2b);
        cf[3][0] = bcasth2(-s2a); cf[3][1] = bcasth2(-s2b);
    }
    __syncthreads();                    // XS/XD visible

    // ---- A base fragments (loaded once) ----
    uint32_t ab[4][4];
    {
        const uint32_t xbase = sb + (v ? SMX_XD : SMX_XS);
        const int arow = wm + (l & 15);
        const uint32_t rowaddr = xbase + arow * 128;
        const int lx = (l >> 4);
#pragma unroll 4
        for (int ks = 0; ks < 4; ++ks)
            ldsm4(ab[ks][0], ab[ks][1], ab[ks][2], ab[ks][3],
                  rowaddr + (((ks * 2 + lx) ^ (arow & 7)) << 4));
    }

    float acc[16][4];
#pragma unroll
    for (int nt = 0; nt < 16; ++nt)
#pragma unroll
        for (int e = 0; e < 4; ++e) acc[nt][e] = 0.0f;

    const int nrowbase = (l & 15);
    const int lx = (l >> 4);

    for (int kb = 0; kb < 5; ++kb) {
        if (kb < 4) { CP_ASYNC_WAIT1(); } else { CP_ASYNC_WAIT0(); }
        __syncthreads();                // stage kb ready for all warps
        const uint32_t bst = sb + SMX_B + (kb & 1) * 16384;

#pragma unroll 4
        for (int ks = 0; ks < 4; ++ks) {
            uint32_t af[4];
            if (kb == 0) {
#pragma unroll
                for (int j = 0; j < 4; ++j) af[j] = ab[ks][j];
            } else {
#pragma unroll
                for (int j = 0; j < 4; ++j) af[j] = hmul2u(ab[ks][j], cf[kb - 1][j & 1]);
            }
#pragma unroll 2
            for (int half = 0; half < 2; ++half) {
                uint32_t bfr[8][2];
#pragma unroll 4
                for (int p = 0; p < 4; ++p) {
                    int nrow = (half * 4 + p) * 16 + nrowbase;
                    uint32_t addr = bst + nrow * 128 +
                                    (((ks * 2 + lx) ^ (nrow & 7)) << 4);
                    uint32_t q0, q1, q2, q3;
                    ldsm4(q0, q1, q2, q3, addr);
                    bfr[2 * p][0] = q0; bfr[2 * p][1] = q2;
                    bfr[2 * p + 1][0] = q1; bfr[2 * p + 1][1] = q3;
                }
#pragma unroll 8
                for (int nt = 0; nt < 8; ++nt)
                    mma16816(acc[half * 8 + nt], af, bfr[nt]);
            }
        }
        __syncthreads();                // stage (kb&1) fully consumed
        if (kb + 2 < 5) {
            const __half* Bsrc = BhBase + (size_t)(kb + 2) * (COUT * CIN);
            uint32_t sdst = sb + SMX_B + (kb & 1) * 16384;
#pragma unroll 4
            for (int j = 0; j < 4; ++j) {
                int i = tid + j * 256;
                int o = i >> 3, ch = i & 7;
                cp_async16(sdst + o * 128 + ((ch ^ (o & 7)) << 4),
                           Bsrc + (size_t)o * CIN + ch * 8);
            }
            CP_ASYNC_COMMIT();
        }
    }

    // ---- epilogue: fp16 raw store + fused stats ----
    {
        __half* rbase = g_raw + ((size_t)v * ROWS_PER_VAR + (size_t)b * 128 + mhalf * 64) * COUT;
        const int rlo = wm + (l >> 2);
        float* sStatv = sStat + v * 256;
#pragma unroll 16
        for (int nt = 0; nt < 16; ++nt) {
            int c = nt * 8 + 2 * (l & 3);
            *(uint32_t*)(rbase + (size_t)rlo * COUT + c) = packh2(acc[nt][0], acc[nt][1]);
            *(uint32_t*)(rbase + (size_t)(rlo + 8) * COUT + c) = packh2(acc[nt][2], acc[nt][3]);
            float s0 = acc[nt][0] + acc[nt][2];
            float s1 = acc[nt][1] + acc[nt][3];
            float q0 = acc[nt][0] * acc[nt][0] + acc[nt][2] * acc[nt][2];
            float q1 = acc[nt][1] * acc[nt][1] + acc[nt][3] * acc[nt][3];
#pragma unroll
            for (int off = 4; off < 32; off <<= 1) {
                s0 += __shfl_xor_sync(0xFFFFFFFFu, s0, off);
                q0 += __shfl_xor_sync(0xFFFFFFFFu, q0, off);
                s1 += __shfl_xor_sync(0xFFFFFFFFu, s1, off);
                q1 += __shfl_xor_sync(0xFFFFFFFFu, q1, off);
            }
            if (l < 4) {
                atomicAdd(&sStatv[c], s0);
                atomicAdd(&sStatv[c + 1], s1);
                atomicAdd(&sStatv[128 + c], q0);
                atomicAdd(&sStatv[128 + c + 1], q1);
            }
        }
    }

    __syncthreads();
    atomicAdd(&g_sum[tid], sStat[(tid >> 7) * 256 + (tid & 127)]);
    atomicAdd(&g_sumsq[tid], sStat[(tid >> 7) * 256 + 128 + (tid & 127)]);
}

// ================= normalize: BN(train) + LeakyReLU, fp16 raw -> fp32 out =================
__global__ void __launch_bounds__(256) norm_kernel(float* __restrict__ out,
                                                   const float* __restrict__ gr,
                                                   const float* __restrict__ br,
                                                   const float* __restrict__ gi,
                                                   const float* __restrict__ bi) {
    __shared__ float sA[2 * COUT], sB[2 * COUT];
    const int tid = threadIdx.x;
    {
        int v = tid >> 7, o = tid & 127;
        const float inv = 1.0f / (float)ROWS_PER_VAR;
        float mean = g_sum[tid] * inv;
        float var  = g_sumsq[tid] * inv - mean * mean;
        float g  = v ? gi[o] : gr[o];
        float be = v ? bi[o] : br[o];
        float a = g * rsqrtf(var + EPS_BN);
        sA[tid] = a;
        sB[tid] = be - mean * a;
    }
    __syncthreads();

    const int vb = blockIdx.x >> 11;              // grid 4096: variant fixed per block
    const int base = (blockIdx.x & 2047) * 256 + tid;
    const int idx = vb * 128 + (tid & 15) * 8;    // channel block fixed per thread
    float cA[8], cB[8];
#pragma unroll 8
    for (int e = 0; e < 8; ++e) { cA[e] = sA[idx + e]; cB[e] = sB[idx + e]; }

    const uint4* rp = (const uint4*)g_raw + (size_t)vb * 2097152;
    float4* op = (float4*)out + (size_t)vb * 4194304;
#pragma unroll 4
    for (int k = 0; k < 4; ++k) {
        int i8 = base + k * 524288;               // < 2097152
        uint4 rv = rp[i8];
        float2 f0 = __half22float2(*(__half2*)&rv.x);
        float2 f1 = __half22float2(*(__half2*)&rv.y);
        float2 f2 = __half22float2(*(__half2*)&rv.z);
        float2 f3 = __half22float2(*(__half2*)&rv.w);
        float y0 = fmaf(cA[0], f0.x, cB[0]);
        float y1 = fmaf(cA[1], f0.y, cB[1]);
        float y2 = fmaf(cA[2], f1.x, cB[2]);
        float y3 = fmaf(cA[3], f1.y, cB[3]);
        float y4 = fmaf(cA[4], f2.x, cB[4]);
        float y5 = fmaf(cA[5], f2.y, cB[5]);
        float y6 = fmaf(cA[6], f3.x, cB[6]);
        float y7 = fmaf(cA[7], f3.y, cB[7]);
        y0 = y0 >= 0.f ? y0 : ALPHA * y0;
        y1 = y1 >= 0.f ? y1 : ALPHA * y1;
        y2 = y2 >= 0.f ? y2 : ALPHA * y2;
        y3 = y3 >= 0.f ? y3 : ALPHA * y3;
        y4 = y4 >= 0.f ? y4 : ALPHA * y4;
        y5 = y5 >= 0.f ? y5 : ALPHA * y5;
        y6 = y6 >= 0.f ? y6 : ALPHA * y6;
        y7 = y7 >= 0.f ? y7 : ALPHA * y7;
        op[2 * i8]     = make_float4(y0, y1, y2, y3);
        op[2 * i8 + 1] = make_float4(y4, y5, y6, y7);
    }
}

// ================= launch =================
extern "C" void kernel_launch(void* const* d_in, const int* in_sizes, int n_in,
                              void* d_out, int out_size) {
    const float* xr = (const float*)d_in[0];
    const float* xi = (const float*)d_in[1];
    const float* fl = (const float*)d_in[2];
    const float* gr = (const float*)d_in[3];
    const float* br = (const float*)d_in[4];
    const float* gi = (const float*)d_in[5];
    const float* bi = (const float*)d_in[6];
    float* out = (float*)d_out;

    cudaFuncSetAttribute(fourier_main, cudaFuncAttributeMaxDynamicSharedMemorySize, SMX_TOTAL);

    prep_T<<<9, 256>>>(fl);
    prep_B2<<<5 * HH, 256>>>();
    fourier_main<<<2 * NB * HH, 256, SMX_TOTAL>>>(xr, xi);
    norm_kernel<<<4096, 256>>>(out, gr, br, gi, bi);
}